// round 6
// baseline (speedup 1.0000x reference)
#include <cuda_runtime.h>

#define NN 50000
#define DD 128
#define EE 800000
#define EPSL 1e-5f

#define SCH 512
#define SNB ((NN + SCH - 1) / SCH)   // 98

// ---------------- scratch (device globals; no allocation allowed) -------------
__device__ float g_dinv[NN];
__device__ float g_tmpA[NN * DD];
__device__ float g_tmpB[NN * DD];
__device__ float g_x1[NN * DD];    // x after layer0 + residual
__device__ int   g_cnt[NN];
__device__ int   g_start[NN];
__device__ int   g_cursor[NN];
__device__ int   g_esrc[EE];       // edge srcs bucketed by dst (CSR)
__device__ int   g_csum[SNB];

// ---------------- CSR build ----------------------------------------------------
__global__ void k_zero() {
    int i = blockIdx.x * blockDim.x + threadIdx.x;
    if (i < NN) g_cnt[i] = 0;
}

__global__ void k_hist(const int* __restrict__ dst) {
    int e = blockIdx.x * blockDim.x + threadIdx.x;
    if (e < EE) atomicAdd(&g_cnt[dst[e]], 1);
}

__global__ void k_dinv() {
    int i = blockIdx.x * blockDim.x + threadIdx.x;
    if (i < NN) g_dinv[i] = rsqrtf(1.0f + (float)g_cnt[i]);
}

__global__ void __launch_bounds__(SCH) k_scan_a() {
    __shared__ int sm[SCH];
    int t = threadIdx.x;
    int i = blockIdx.x * SCH + t;
    sm[t] = (i < NN) ? g_cnt[i] : 0;
    __syncthreads();
    for (int off = SCH / 2; off > 0; off >>= 1) {
        if (t < off) sm[t] += sm[t + off];
        __syncthreads();
    }
    if (t == 0) g_csum[blockIdx.x] = sm[0];
}

__global__ void __launch_bounds__(SCH) k_scan_c() {
    __shared__ int sm[SCH];
    __shared__ int base;
    int t = threadIdx.x;
    int i = blockIdx.x * SCH + t;
    int v = (i < NN) ? g_cnt[i] : 0;
    sm[t] = v;
    if (t == 0) {
        int run = 0;
        for (int j = 0; j < blockIdx.x; j++) run += g_csum[j];
        base = run;
    }
    __syncthreads();
    for (int off = 1; off < SCH; off <<= 1) {
        int x = (t >= off) ? sm[t - off] : 0;
        __syncthreads();
        sm[t] += x;
        __syncthreads();
    }
    if (i < NN) {
        int excl = sm[t] - v + base;
        g_start[i] = excl;
        g_cursor[i] = excl;
    }
}

__global__ void k_bucket(const int* __restrict__ src, const int* __restrict__ dst) {
    int e = blockIdx.x * blockDim.x + threadIdx.x;
    if (e < EE) {
        int pos = atomicAdd(&g_cursor[dst[e]], 1);
        g_esrc[pos] = src[e];
    }
}

// ---------------- fused LN + ReLU + GEMM + dinv prescale (layer 0) ------------
#define TR 64
#define KT 32
__global__ void __launch_bounds__(256) k_ln_gemm(const float* __restrict__ h,
                          const float* __restrict__ g,
                          const float* __restrict__ bt,
                          const float* __restrict__ W,
                          float* __restrict__ tout) {
    __shared__ float As[TR * DD];    // 32KB
    __shared__ float Ws[KT * DD];    // 16KB

    int tid = threadIdx.x;
    int lane = tid & 31;
    int w = tid >> 5;
    int row0 = blockIdx.x * TR;

    for (int r = w; r < TR; r += 8) {
        int row = row0 + r;
        float4 v = make_float4(0.f, 0.f, 0.f, 0.f);
        if (row < NN) v = ((const float4*)(h + (size_t)row * DD))[lane];
        float s = v.x + v.y + v.z + v.w;
        #pragma unroll
        for (int o = 16; o; o >>= 1) s += __shfl_xor_sync(0xffffffffu, s, o);
        float mu = s * (1.0f / DD);
        float dx = v.x - mu, dy = v.y - mu, dz = v.z - mu, dw = v.w - mu;
        float q = dx * dx + dy * dy + dz * dz + dw * dw;
        #pragma unroll
        for (int o = 16; o; o >>= 1) q += __shfl_xor_sync(0xffffffffu, q, o);
        float rstd = rsqrtf(q * (1.0f / DD) + EPSL);
        float4 gg = ((const float4*)g)[lane];
        float4 bb = ((const float4*)bt)[lane];
        float4 o4;
        o4.x = fmaxf(fmaf(dx * rstd, gg.x, bb.x), 0.f);
        o4.y = fmaxf(fmaf(dy * rstd, gg.y, bb.y), 0.f);
        o4.z = fmaxf(fmaf(dz * rstd, gg.z, bb.z), 0.f);
        o4.w = fmaxf(fmaf(dw * rstd, gg.w, bb.w), 0.f);
        ((float4*)(As + r * DD))[lane] = o4;
    }

    float acc[8][4];
    #pragma unroll
    for (int i = 0; i < 8; i++)
        #pragma unroll
        for (int j = 0; j < 4; j++) acc[i][j] = 0.f;

    const float* aw = As + w * 8 * DD;

    for (int k0 = 0; k0 < DD; k0 += KT) {
        __syncthreads();
        {
            const float4* W4 = (const float4*)(W + (size_t)k0 * DD);
            float4* Ws4 = (float4*)Ws;
            #pragma unroll
            for (int i = tid; i < KT * DD / 4; i += 256) Ws4[i] = W4[i];
        }
        __syncthreads();

        #pragma unroll 8
        for (int kk = 0; kk < KT; kk++) {
            float4 wv = ((const float4*)(Ws + kk * DD))[lane];
            #pragma unroll
            for (int i = 0; i < 8; i++) {
                float va = aw[i * DD + k0 + kk];
                acc[i][0] = fmaf(va, wv.x, acc[i][0]);
                acc[i][1] = fmaf(va, wv.y, acc[i][1]);
                acc[i][2] = fmaf(va, wv.z, acc[i][2]);
                acc[i][3] = fmaf(va, wv.w, acc[i][3]);
            }
        }
    }

    #pragma unroll
    for (int i = 0; i < 8; i++) {
        int row = row0 + w * 8 + i;
        if (row < NN) {
            float dv = g_dinv[row];
            float4 o;
            o.x = acc[i][0] * dv;
            o.y = acc[i][1] * dv;
            o.z = acc[i][2] * dv;
            o.w = acc[i][3] * dv;
            ((float4*)(tout + (size_t)row * DD))[lane] = o;
        }
    }
}

// ---------------- fused accum + LN + ReLU + GEMM ------------------------------
// h[i] = b + dinv[i]*(tin[i] + sum tin[src]) (+ res[i]); optionally write h;
// then tout[i] = dinv[i]*(ReLU(LN(h_i)) @ W)
__global__ void __launch_bounds__(256) k_fused(const float* __restrict__ tin,
                       float* __restrict__ tout,
                       const float* __restrict__ b,
                       const float* __restrict__ res,
                       float* __restrict__ hout,
                       const float* __restrict__ g,
                       const float* __restrict__ bt,
                       const float* __restrict__ W) {
    __shared__ float As[TR * DD];    // 32KB
    __shared__ float Ws[KT * DD];    // 16KB

    int tid = threadIdx.x;
    int lane = tid & 31;
    int w = tid >> 5;
    int row0 = blockIdx.x * TR;

    const float4* T = (const float4*)tin;
    float4 gg = ((const float4*)g)[lane];
    float4 bbln = ((const float4*)bt)[lane];
    float4 bac = ((const float4*)b)[lane];

    // accum + LN + ReLU phase: warp w handles rows w*8 .. w*8+7
    #pragma unroll 1
    for (int i = 0; i < 8; i++) {
        int r = w * 8 + i;
        int row = row0 + r;
        if (row < NN) {
            int s0 = g_start[row];
            int cnt = g_cnt[row];

            float4 a0 = T[(size_t)row * 32 + lane];   // self loop
            float4 a1 = make_float4(0.f, 0.f, 0.f, 0.f);
            float4 a2 = make_float4(0.f, 0.f, 0.f, 0.f);
            float4 a3 = make_float4(0.f, 0.f, 0.f, 0.f);

            int e = 0;
            for (; e + 4 <= cnt; e += 4) {
                int i0 = g_esrc[s0 + e + 0];
                int i1 = g_esrc[s0 + e + 1];
                int i2 = g_esrc[s0 + e + 2];
                int i3 = g_esrc[s0 + e + 3];
                float4 v0 = T[(size_t)i0 * 32 + lane];
                float4 v1 = T[(size_t)i1 * 32 + lane];
                float4 v2 = T[(size_t)i2 * 32 + lane];
                float4 v3 = T[(size_t)i3 * 32 + lane];
                a0.x += v0.x; a0.y += v0.y; a0.z += v0.z; a0.w += v0.w;
                a1.x += v1.x; a1.y += v1.y; a1.z += v1.z; a1.w += v1.w;
                a2.x += v2.x; a2.y += v2.y; a2.z += v2.z; a2.w += v2.w;
                a3.x += v3.x; a3.y += v3.y; a3.z += v3.z; a3.w += v3.w;
            }
            for (; e < cnt; e++) {
                int i0 = g_esrc[s0 + e];
                float4 v0 = T[(size_t)i0 * 32 + lane];
                a0.x += v0.x; a0.y += v0.y; a0.z += v0.z; a0.w += v0.w;
            }
            a0.x += a1.x + a2.x + a3.x;
            a0.y += a1.y + a2.y + a3.y;
            a0.z += a1.z + a2.z + a3.z;
            a0.w += a1.w + a2.w + a3.w;

            float dv = g_dinv[row];
            float4 hv;
            hv.x = fmaf(dv, a0.x, bac.x);
            hv.y = fmaf(dv, a0.y, bac.y);
            hv.z = fmaf(dv, a0.z, bac.z);
            hv.w = fmaf(dv, a0.w, bac.w);
            if (res) {
                float4 rr = ((const float4*)res)[(size_t)row * 32 + lane];
                hv.x += rr.x; hv.y += rr.y; hv.z += rr.z; hv.w += rr.w;
            }
            if (hout) ((float4*)hout)[(size_t)row * 32 + lane] = hv;

            // LayerNorm + ReLU in registers
            float s = hv.x + hv.y + hv.z + hv.w;
            #pragma unroll
            for (int o = 16; o; o >>= 1) s += __shfl_xor_sync(0xffffffffu, s, o);
            float mu = s * (1.0f / DD);
            float dx = hv.x - mu, dy = hv.y - mu, dz = hv.z - mu, dw2 = hv.w - mu;
            float q = dx * dx + dy * dy + dz * dz + dw2 * dw2;
            #pragma unroll
            for (int o = 16; o; o >>= 1) q += __shfl_xor_sync(0xffffffffu, q, o);
            float rstd = rsqrtf(q * (1.0f / DD) + EPSL);
            float4 o4;
            o4.x = fmaxf(fmaf(dx * rstd, gg.x, bbln.x), 0.f);
            o4.y = fmaxf(fmaf(dy * rstd, gg.y, bbln.y), 0.f);
            o4.z = fmaxf(fmaf(dz * rstd, gg.z, bbln.z), 0.f);
            o4.w = fmaxf(fmaf(dw2 * rstd, gg.w, bbln.w), 0.f);
            ((float4*)(As + r * DD))[lane] = o4;
        } else {
            ((float4*)(As + r * DD))[lane] = make_float4(0.f, 0.f, 0.f, 0.f);
        }
    }

    // GEMM phase
    float acc[8][4];
    #pragma unroll
    for (int i = 0; i < 8; i++)
        #pragma unroll
        for (int j = 0; j < 4; j++) acc[i][j] = 0.f;

    const float* aw = As + w * 8 * DD;

    for (int k0 = 0; k0 < DD; k0 += KT) {
        __syncthreads();
        {
            const float4* W4 = (const float4*)(W + (size_t)k0 * DD);
            float4* Ws4 = (float4*)Ws;
            #pragma unroll
            for (int i = tid; i < KT * DD / 4; i += 256) Ws4[i] = W4[i];
        }
        __syncthreads();

        #pragma unroll 8
        for (int kk = 0; kk < KT; kk++) {
            float4 wv = ((const float4*)(Ws + kk * DD))[lane];
            #pragma unroll
            for (int i = 0; i < 8; i++) {
                float va = aw[i * DD + k0 + kk];
                acc[i][0] = fmaf(va, wv.x, acc[i][0]);
                acc[i][1] = fmaf(va, wv.y, acc[i][1]);
                acc[i][2] = fmaf(va, wv.z, acc[i][2]);
                acc[i][3] = fmaf(va, wv.w, acc[i][3]);
            }
        }
    }

    #pragma unroll
    for (int i = 0; i < 8; i++) {
        int row = row0 + w * 8 + i;
        if (row < NN) {
            float dv = g_dinv[row];
            float4 o;
            o.x = acc[i][0] * dv;
            o.y = acc[i][1] * dv;
            o.z = acc[i][2] * dv;
            o.w = acc[i][3] * dv;
            ((float4*)(tout + (size_t)row * DD))[lane] = o;
        }
    }
}

// ---------------- final per-node gather accumulate ----------------------------
__global__ void __launch_bounds__(256) k_accum(const float* __restrict__ tin,
                        float* __restrict__ out,
                        const float* __restrict__ b,
                        const float* __restrict__ res) {
    int node = (blockIdx.x * blockDim.x + threadIdx.x) >> 5;
    int lane = threadIdx.x & 31;
    if (node >= NN) return;

    const float4* T = (const float4*)tin;
    int s0 = g_start[node];
    int cnt = g_cnt[node];

    float4 a[8];
    a[0] = T[(size_t)node * 32 + lane];
    #pragma unroll
    for (int j = 1; j < 8; j++) a[j] = make_float4(0.f, 0.f, 0.f, 0.f);

    int e = 0;
    for (; e + 8 <= cnt; e += 8) {
        int idx[8];
        #pragma unroll
        for (int j = 0; j < 8; j++) idx[j] = g_esrc[s0 + e + j];
        #pragma unroll
        for (int j = 0; j < 8; j++) {
            float4 v = T[(size_t)idx[j] * 32 + lane];
            a[j].x += v.x; a[j].y += v.y; a[j].z += v.z; a[j].w += v.w;
        }
    }
    for (; e < cnt; e++) {
        int i0 = g_esrc[s0 + e];
        float4 v = T[(size_t)i0 * 32 + lane];
        a[0].x += v.x; a[0].y += v.y; a[0].z += v.z; a[0].w += v.w;
    }
    #pragma unroll
    for (int j = 1; j < 8; j++) {
        a[0].x += a[j].x; a[0].y += a[j].y; a[0].z += a[j].z; a[0].w += a[j].w;
    }

    float dv = g_dinv[node];
    float4 bb = ((const float4*)b)[lane];
    float4 o;
    o.x = fmaf(dv, a[0].x, bb.x);
    o.y = fmaf(dv, a[0].y, bb.y);
    o.z = fmaf(dv, a[0].z, bb.z);
    o.w = fmaf(dv, a[0].w, bb.w);
    if (res) {
        float4 r = ((const float4*)(res))[(size_t)node * 32 + lane];
        o.x += r.x; o.y += r.y; o.z += r.z; o.w += r.w;
    }
    ((float4*)out)[(size_t)node * 32 + lane] = o;
}

// ---------------- launch ------------------------------------------------------
extern "C" void kernel_launch(void* const* d_in, const int* in_sizes, int n_in,
                              void* d_out, int out_size) {
    const float* x   = (const float*)d_in[0];
    const int*   ei  = (const int*)d_in[1];
    const int*   src = ei;
    const int*   dst = ei + EE;
    const float* lng0 = (const float*)d_in[2];
    const float* lnb0 = (const float*)d_in[3];
    const float* W0   = (const float*)d_in[4];
    const float* b0   = (const float*)d_in[5];
    const float* lng1 = (const float*)d_in[6];
    const float* lnb1 = (const float*)d_in[7];
    const float* W1   = (const float*)d_in[8];
    const float* b1   = (const float*)d_in[9];
    const float* lng2 = (const float*)d_in[10];
    const float* lnb2 = (const float*)d_in[11];
    const float* W2   = (const float*)d_in[12];
    const float* b2   = (const float*)d_in[13];
    float* out = (float*)d_out;

    float* d_tA;  cudaGetSymbolAddress((void**)&d_tA, g_tmpA);
    float* d_tB;  cudaGetSymbolAddress((void**)&d_tB, g_tmpB);
    float* d_x1;  cudaGetSymbolAddress((void**)&d_x1, g_x1);

    const int gemm_blocks = (NN + TR - 1) / TR;
    const int acc_blocks = (NN * 32 + 255) / 256;

    // prep part 1 (dinv needed by gemm0)
    k_zero<<<(NN + 255) / 256, 256>>>();
    k_hist<<<(EE + 255) / 256, 256>>>(dst);
    k_dinv<<<(NN + 255) / 256, 256>>>();

    // layer 0 GEMM (launch #4 -> ncu profile slot)
    k_ln_gemm<<<gemm_blocks, 256>>>(x, lng0, lnb0, W0, d_tA);

    // prep part 2 (CSR for accum)
    k_scan_a<<<SNB, SCH>>>();
    k_scan_c<<<SNB, SCH>>>();
    k_bucket<<<(EE + 255) / 256, 256>>>(src, dst);

    // fused: accum0 (res=x, write x1) + LN1 + GEMM1  : tA -> tB
    k_fused<<<gemm_blocks, 256>>>(d_tA, d_tB, b0, x, d_x1, lng1, lnb1, W1);
    // fused: accum1 (no res, no write) + LN2 + GEMM2 : tB -> tA
    k_fused<<<gemm_blocks, 256>>>(d_tB, d_tA, b1, nullptr, nullptr, lng2, lnb2, W2);

    // final accum: out = b2 + dinv*(self+sum) + x1
    k_accum<<<acc_blocks, 256>>>(d_tA, out, b2, d_x1);
}

// round 8
// speedup vs baseline: 1.1296x; 1.1296x over previous
#include <cuda_runtime.h>
#include <cstdint>

#define NN 50000
#define DD 128
#define EE 800000
#define EPSL 1e-5f

#define SCH 512
#define SNB ((NN + SCH - 1) / SCH)   // 98

// GEMM tiling
#define BM 128
#define KT 64
#define AP 132              // As row stride (floats), pad for conflict-free frags
#define WP 136              // Ws row stride
#define SMEM_BYTES ((BM * AP + KT * WP) * 4)   // 102400 B

// ---------------- scratch (device globals; no allocation allowed) -------------
__device__ float g_dinv[NN];
__device__ float g_tmpA[NN * DD];
__device__ float g_tmpB[NN * DD];
__device__ float g_x1[NN * DD];
__device__ int   g_cnt[NN];
__device__ int   g_start[NN];
__device__ int   g_cursor[NN];
__device__ int   g_esrc[EE];
__device__ int   g_csum[SNB];

// ---------------- CSR build ----------------------------------------------------
__global__ void k_zero() {
    int i = blockIdx.x * blockDim.x + threadIdx.x;
    if (i < NN) g_cnt[i] = 0;
}

__global__ void k_hist(const int* __restrict__ dst) {
    int e = blockIdx.x * blockDim.x + threadIdx.x;
    if (e < EE) atomicAdd(&g_cnt[dst[e]], 1);
}

__global__ void k_dinv() {
    int i = blockIdx.x * blockDim.x + threadIdx.x;
    if (i < NN) g_dinv[i] = rsqrtf(1.0f + (float)g_cnt[i]);
}

__global__ void __launch_bounds__(SCH) k_scan_a() {
    __shared__ int sm[SCH];
    int t = threadIdx.x;
    int i = blockIdx.x * SCH + t;
    sm[t] = (i < NN) ? g_cnt[i] : 0;
    __syncthreads();
    for (int off = SCH / 2; off > 0; off >>= 1) {
        if (t < off) sm[t] += sm[t + off];
        __syncthreads();
    }
    if (t == 0) g_csum[blockIdx.x] = sm[0];
}

__global__ void __launch_bounds__(SCH) k_scan_c() {
    __shared__ int sm[SCH];
    __shared__ int base;
    int t = threadIdx.x;
    int i = blockIdx.x * SCH + t;
    int v = (i < NN) ? g_cnt[i] : 0;
    sm[t] = v;
    if (t == 0) {
        int run = 0;
        for (int j = 0; j < blockIdx.x; j++) run += g_csum[j];
        base = run;
    }
    __syncthreads();
    for (int off = 1; off < SCH; off <<= 1) {
        int x = (t >= off) ? sm[t - off] : 0;
        __syncthreads();
        sm[t] += x;
        __syncthreads();
    }
    if (i < NN) {
        int excl = sm[t] - v + base;
        g_start[i] = excl;
        g_cursor[i] = excl;
    }
}

__global__ void k_bucket(const int* __restrict__ src, const int* __restrict__ dst) {
    int e = blockIdx.x * blockDim.x + threadIdx.x;
    if (e < EE) {
        int pos = atomicAdd(&g_cursor[dst[e]], 1);
        g_esrc[pos] = src[e];
    }
}

// ---------------- TF32 helpers -------------------------------------------------
__device__ __forceinline__ float f2tf(float f) {
    uint32_t u;
    asm("cvt.rna.tf32.f32 %0, %1;" : "=r"(u) : "f"(f));
    return __uint_as_float(u);
}

__device__ __forceinline__ void mma_tf32(float4& c, const uint32_t a0, const uint32_t a1,
                                         const uint32_t a2, const uint32_t a3,
                                         const uint32_t b0, const uint32_t b1) {
    asm volatile("mma.sync.aligned.m16n8k8.row.col.f32.tf32.tf32.f32 "
                 "{%0,%1,%2,%3}, {%4,%5,%6,%7}, {%8,%9}, {%0,%1,%2,%3};"
                 : "+f"(c.x), "+f"(c.y), "+f"(c.z), "+f"(c.w)
                 : "r"(a0), "r"(a1), "r"(a2), "r"(a3), "r"(b0), "r"(b1));
}

// ---------------- fused LN + ReLU + TF32 GEMM + dinv prescale ------------------
// tout[i] = dinv[i] * ( ReLU( LN(h_i)*g + bt ) @ W )
// Block 256 thr; tile M=128 x N=128; k chunks of 64.
__global__ void __launch_bounds__(256) k_ln_gemm(const float* __restrict__ h,
                          const float* __restrict__ g,
                          const float* __restrict__ bt,
                          const float* __restrict__ W,
                          float* __restrict__ tout) {
    extern __shared__ float sm[];
    float* As = sm;             // [128][AP]
    float* Ws = sm + BM * AP;   // [KT][WP]

    int tid = threadIdx.x;
    int lane = tid & 31;
    int w = tid >> 5;
    int qid = lane >> 2;        // 0..7
    int tq = lane & 3;          // 0..3
    int row0 = blockIdx.x * BM;

    // --- LN + ReLU phase: warp w handles rows w, w+8, ..., w+120; cvt to tf32 ---
    for (int r = w; r < BM; r += 8) {
        int row = row0 + r;
        float4 v = make_float4(0.f, 0.f, 0.f, 0.f);
        if (row < NN) v = ((const float4*)(h + (size_t)row * DD))[lane];
        float s = v.x + v.y + v.z + v.w;
        #pragma unroll
        for (int o = 16; o; o >>= 1) s += __shfl_xor_sync(0xffffffffu, s, o);
        float mu = s * (1.0f / DD);
        float dx = v.x - mu, dy = v.y - mu, dz = v.z - mu, dw = v.w - mu;
        float q = dx * dx + dy * dy + dz * dz + dw * dw;
        #pragma unroll
        for (int o = 16; o; o >>= 1) q += __shfl_xor_sync(0xffffffffu, q, o);
        float rstd = rsqrtf(q * (1.0f / DD) + EPSL);
        float4 gg = ((const float4*)g)[lane];
        float4 bb = ((const float4*)bt)[lane];
        float4 o4;
        o4.x = f2tf(fmaxf(fmaf(dx * rstd, gg.x, bb.x), 0.f));
        o4.y = f2tf(fmaxf(fmaf(dy * rstd, gg.y, bb.y), 0.f));
        o4.z = f2tf(fmaxf(fmaf(dz * rstd, gg.z, bb.z), 0.f));
        o4.w = f2tf(fmaxf(fmaf(dw * rstd, gg.w, bb.w), 0.f));
        *(float4*)(As + r * AP + lane * 4) = o4;
    }

    // warp tile: warp_m in 0..3 (M=32 each), warp_n in 0..1 (N=64 each)
    int warp_m = w & 3;
    int warp_n = w >> 2;
    int m0 = warp_m * 32;
    int nb = warp_n * 64;

    float4 c[2][8];
    #pragma unroll
    for (int mt = 0; mt < 2; mt++)
        #pragma unroll
        for (int nt = 0; nt < 8; nt++) c[mt][nt] = make_float4(0.f, 0.f, 0.f, 0.f);

    for (int k0 = 0; k0 < DD; k0 += KT) {
        __syncthreads();   // As ready (first iter) / Ws reads done (later iters)
        // stage W[k0:k0+KT, :] into Ws with tf32 rounding
        for (int idx = tid; idx < KT * DD / 4; idx += 256) {
            int kk = idx >> 5;          // DD/4 = 32
            int c4 = idx & 31;
            float4 wv = *(const float4*)(W + (size_t)(k0 + kk) * DD + c4 * 4);
            wv.x = f2tf(wv.x); wv.y = f2tf(wv.y); wv.z = f2tf(wv.z); wv.w = f2tf(wv.w);
            *(float4*)(Ws + kk * WP + c4 * 4) = wv;
        }
        __syncthreads();

        #pragma unroll
        for (int ks = 0; ks < KT / 8; ks++) {
            int kb = ks * 8;
            int ka = k0 + kb;          // global k offset into As (BUGFIX: add k0)
            // A fragments for 2 m16 tiles
            uint32_t a[2][4];
            #pragma unroll
            for (int mt = 0; mt < 2; mt++) {
                int ra = m0 + mt * 16 + qid;
                a[mt][0] = __float_as_uint(As[ra * AP + ka + tq]);
                a[mt][1] = __float_as_uint(As[(ra + 8) * AP + ka + tq]);
                a[mt][2] = __float_as_uint(As[ra * AP + ka + tq + 4]);
                a[mt][3] = __float_as_uint(As[(ra + 8) * AP + ka + tq + 4]);
            }
            #pragma unroll
            for (int nt = 0; nt < 8; nt++) {
                int col = nb + nt * 8 + qid;
                uint32_t b0 = __float_as_uint(Ws[(kb + tq) * WP + col]);
                uint32_t b1 = __float_as_uint(Ws[(kb + tq + 4) * WP + col]);
                mma_tf32(c[0][nt], a[0][0], a[0][1], a[0][2], a[0][3], b0, b1);
                mma_tf32(c[1][nt], a[1][0], a[1][1], a[1][2], a[1][3], b0, b1);
            }
        }
    }

    // epilogue: scale by dinv[row], write float2 pairs
    #pragma unroll
    for (int mt = 0; mt < 2; mt++) {
        int ra = row0 + m0 + mt * 16 + qid;
        int rb = ra + 8;
        float dva = (ra < NN) ? g_dinv[ra] : 0.f;
        float dvb = (rb < NN) ? g_dinv[rb] : 0.f;
        #pragma unroll
        for (int nt = 0; nt < 8; nt++) {
            int col = nb + nt * 8 + 2 * tq;
            if (ra < NN) {
                float2 o = make_float2(c[mt][nt].x * dva, c[mt][nt].y * dva);
                *(float2*)(tout + (size_t)ra * DD + col) = o;
            }
            if (rb < NN) {
                float2 o = make_float2(c[mt][nt].z * dvb, c[mt][nt].w * dvb);
                *(float2*)(tout + (size_t)rb * DD + col) = o;
            }
        }
    }
}

// ---------------- per-node gather accumulate ----------------------------------
// out[i] = b + dinv[i]*(tin[i] + sum_{e in CSR[i]} tin[src_e]) (+ res[i])
__global__ void __launch_bounds__(256) k_accum(const float* __restrict__ tin,
                        float* __restrict__ out,
                        const float* __restrict__ b,
                        const float* __restrict__ res) {
    int node = (blockIdx.x * blockDim.x + threadIdx.x) >> 5;
    int lane = threadIdx.x & 31;
    if (node >= NN) return;

    const float4* T = (const float4*)tin;
    int s0 = g_start[node];
    int cnt = g_cnt[node];

    float4 a[8];
    a[0] = T[(size_t)node * 32 + lane];
    #pragma unroll
    for (int j = 1; j < 8; j++) a[j] = make_float4(0.f, 0.f, 0.f, 0.f);

    int e = 0;
    for (; e + 8 <= cnt; e += 8) {
        int idx[8];
        #pragma unroll
        for (int j = 0; j < 8; j++) idx[j] = g_esrc[s0 + e + j];
        #pragma unroll
        for (int j = 0; j < 8; j++) {
            float4 v = T[(size_t)idx[j] * 32 + lane];
            a[j].x += v.x; a[j].y += v.y; a[j].z += v.z; a[j].w += v.w;
        }
    }
    for (; e < cnt; e++) {
        int i0 = g_esrc[s0 + e];
        float4 v = T[(size_t)i0 * 32 + lane];
        a[0].x += v.x; a[0].y += v.y; a[0].z += v.z; a[0].w += v.w;
    }
    #pragma unroll
    for (int j = 1; j < 8; j++) {
        a[0].x += a[j].x; a[0].y += a[j].y; a[0].z += a[j].z; a[0].w += a[j].w;
    }

    float dv = g_dinv[node];
    float4 bb = ((const float4*)b)[lane];
    float4 o;
    o.x = fmaf(dv, a[0].x, bb.x);
    o.y = fmaf(dv, a[0].y, bb.y);
    o.z = fmaf(dv, a[0].z, bb.z);
    o.w = fmaf(dv, a[0].w, bb.w);
    if (res) {
        float4 r = ((const float4*)(res))[(size_t)node * 32 + lane];
        o.x += r.x; o.y += r.y; o.z += r.z; o.w += r.w;
    }
    ((float4*)out)[(size_t)node * 32 + lane] = o;
}

// ---------------- launch ------------------------------------------------------
extern "C" void kernel_launch(void* const* d_in, const int* in_sizes, int n_in,
                              void* d_out, int out_size) {
    const float* x   = (const float*)d_in[0];
    const int*   ei  = (const int*)d_in[1];
    const int*   src = ei;
    const int*   dst = ei + EE;
    const float* lng0 = (const float*)d_in[2];
    const float* lnb0 = (const float*)d_in[3];
    const float* W0   = (const float*)d_in[4];
    const float* b0   = (const float*)d_in[5];
    const float* lng1 = (const float*)d_in[6];
    const float* lnb1 = (const float*)d_in[7];
    const float* W1   = (const float*)d_in[8];
    const float* b1   = (const float*)d_in[9];
    const float* lng2 = (const float*)d_in[10];
    const float* lnb2 = (const float*)d_in[11];
    const float* W2   = (const float*)d_in[12];
    const float* b2   = (const float*)d_in[13];
    float* out = (float*)d_out;

    float* d_tA;  cudaGetSymbolAddress((void**)&d_tA, g_tmpA);
    float* d_tB;  cudaGetSymbolAddress((void**)&d_tB, g_tmpB);
    float* d_x1;  cudaGetSymbolAddress((void**)&d_x1, g_x1);

    cudaFuncSetAttribute(k_ln_gemm, cudaFuncAttributeMaxDynamicSharedMemorySize, SMEM_BYTES);

    const int gemm_blocks = (NN + BM - 1) / BM;   // 391
    const int acc_blocks = (NN * 32 + 255) / 256;

    // prep part 1 (dinv needed by gemm0)
    k_zero<<<(NN + 255) / 256, 256>>>();
    k_hist<<<(EE + 255) / 256, 256>>>(dst);
    k_dinv<<<(NN + 255) / 256, 256>>>();

    // layer 0 GEMM (launch #4 -> ncu profile slot): x -> tA
    k_ln_gemm<<<gemm_blocks, 256, SMEM_BYTES>>>(x, lng0, lnb0, W0, d_tA);

    // prep part 2 (CSR for accum)
    k_scan_a<<<SNB, SCH>>>();
    k_scan_c<<<SNB, SCH>>>();
    k_bucket<<<(EE + 255) / 256, 256>>>(src, dst);

    // layer 0 accum: tA (+x) -> x1
    k_accum<<<acc_blocks, 256>>>(d_tA, d_x1, b0, x);

    // layer 1: x1 -> tB ; accum -> tA (h2)
    k_ln_gemm<<<gemm_blocks, 256, SMEM_BYTES>>>(d_x1, lng1, lnb1, W1, d_tB);
    k_accum<<<acc_blocks, 256>>>(d_tB, d_tA, b1, nullptr);

    // layer 2: tA -> tB ; accum (+x1) -> out
    k_ln_gemm<<<gemm_blocks, 256, SMEM_BYTES>>>(d_tA, lng2, lnb2, W2, d_tB);
    k_accum<<<acc_blocks, 256>>>(d_tB, out, b2, d_x1);
}

// round 9
// speedup vs baseline: 1.2594x; 1.1149x over previous
#include <cuda_runtime.h>
#include <cstdint>

#define NN 50000
#define DD 128
#define EE 800000
#define EPSL 1e-5f

#define SCH 512
#define SNB ((NN + SCH - 1) / SCH)   // 98

// GEMM tiling
#define BM 128
#define KT 64
#define AP 132              // As row stride (floats), pad for conflict-free frags
#define WP 136              // Ws row stride
#define SMEM_BYTES ((BM * AP + KT * WP) * 4)   // 102400 B

// ---------------- scratch (device globals; no allocation allowed) -------------
__device__ float g_dinv[NN];
__device__ float g_tmpA[NN * DD];
__device__ float g_tmpB[NN * DD];
__device__ float g_x1[NN * DD];
__device__ int   g_cnt[NN];
__device__ int   g_start[NN];
__device__ int   g_cursor[NN];
__device__ int   g_esrc[EE];
__device__ int   g_csum[SNB];

// ---------------- CSR build ----------------------------------------------------
__global__ void k_zero() {
    int i = blockIdx.x * blockDim.x + threadIdx.x;
    if (i < NN) g_cnt[i] = 0;
}

__global__ void k_hist(const int* __restrict__ dst) {
    int e = blockIdx.x * blockDim.x + threadIdx.x;
    if (e < EE) atomicAdd(&g_cnt[dst[e]], 1);
}

__global__ void k_dinv() {
    int i = blockIdx.x * blockDim.x + threadIdx.x;
    if (i < NN) g_dinv[i] = rsqrtf(1.0f + (float)g_cnt[i]);
}

__global__ void __launch_bounds__(SCH) k_scan_a() {
    __shared__ int sm[SCH];
    int t = threadIdx.x;
    int i = blockIdx.x * SCH + t;
    sm[t] = (i < NN) ? g_cnt[i] : 0;
    __syncthreads();
    for (int off = SCH / 2; off > 0; off >>= 1) {
        if (t < off) sm[t] += sm[t + off];
        __syncthreads();
    }
    if (t == 0) g_csum[blockIdx.x] = sm[0];
}

__global__ void __launch_bounds__(SCH) k_scan_c() {
    __shared__ int sm[SCH];
    __shared__ int base;
    int t = threadIdx.x;
    int i = blockIdx.x * SCH + t;
    int v = (i < NN) ? g_cnt[i] : 0;
    sm[t] = v;
    if (t == 0) {
        int run = 0;
        for (int j = 0; j < blockIdx.x; j++) run += g_csum[j];
        base = run;
    }
    __syncthreads();
    for (int off = 1; off < SCH; off <<= 1) {
        int x = (t >= off) ? sm[t - off] : 0;
        __syncthreads();
        sm[t] += x;
        __syncthreads();
    }
    if (i < NN) {
        int excl = sm[t] - v + base;
        g_start[i] = excl;
        g_cursor[i] = excl;
    }
}

__global__ void k_bucket(const int* __restrict__ src, const int* __restrict__ dst) {
    int e = blockIdx.x * blockDim.x + threadIdx.x;
    if (e < EE) {
        int pos = atomicAdd(&g_cursor[dst[e]], 1);
        g_esrc[pos] = src[e];
    }
}

// ---------------- TF32 helpers -------------------------------------------------
__device__ __forceinline__ float f2tf(float f) {
    uint32_t u;
    asm("cvt.rna.tf32.f32 %0, %1;" : "=r"(u) : "f"(f));
    return __uint_as_float(u);
}

__device__ __forceinline__ void mma_tf32(float4& c, const uint32_t a0, const uint32_t a1,
                                         const uint32_t a2, const uint32_t a3,
                                         const uint32_t b0, const uint32_t b1) {
    asm volatile("mma.sync.aligned.m16n8k8.row.col.f32.tf32.tf32.f32 "
                 "{%0,%1,%2,%3}, {%4,%5,%6,%7}, {%8,%9}, {%0,%1,%2,%3};"
                 : "+f"(c.x), "+f"(c.y), "+f"(c.z), "+f"(c.w)
                 : "r"(a0), "r"(a1), "r"(a2), "r"(a3), "r"(b0), "r"(b1));
}

// ---------------- fused LN + ReLU + TF32 GEMM + dinv prescale ------------------
// tout[i] = dinv[i] * ( ReLU( LN(h_i)*g + bt ) @ W )
// Block 512 thr (16 warps); tile M=128 x N=128; warp tile m32 x n32; k chunks 64.
__global__ void __launch_bounds__(512) k_ln_gemm(const float* __restrict__ h,
                          const float* __restrict__ g,
                          const float* __restrict__ bt,
                          const float* __restrict__ W,
                          float* __restrict__ tout) {
    extern __shared__ float sm[];
    float* As = sm;             // [128][AP]
    float* Ws = sm + BM * AP;   // [KT][WP]

    int tid = threadIdx.x;
    int lane = tid & 31;
    int w = tid >> 5;           // 0..15
    int qid = lane >> 2;        // 0..7
    int tq = lane & 3;          // 0..3
    int row0 = blockIdx.x * BM;

    // --- LN + ReLU phase: warp w handles rows w, w+16, ..., w+112 ---
    for (int r = w; r < BM; r += 16) {
        int row = row0 + r;
        float4 v = make_float4(0.f, 0.f, 0.f, 0.f);
        if (row < NN) v = ((const float4*)(h + (size_t)row * DD))[lane];
        float s = v.x + v.y + v.z + v.w;
        #pragma unroll
        for (int o = 16; o; o >>= 1) s += __shfl_xor_sync(0xffffffffu, s, o);
        float mu = s * (1.0f / DD);
        float dx = v.x - mu, dy = v.y - mu, dz = v.z - mu, dw = v.w - mu;
        float q = dx * dx + dy * dy + dz * dz + dw * dw;
        #pragma unroll
        for (int o = 16; o; o >>= 1) q += __shfl_xor_sync(0xffffffffu, q, o);
        float rstd = rsqrtf(q * (1.0f / DD) + EPSL);
        float4 gg = ((const float4*)g)[lane];
        float4 bb = ((const float4*)bt)[lane];
        float4 o4;
        o4.x = f2tf(fmaxf(fmaf(dx * rstd, gg.x, bb.x), 0.f));
        o4.y = f2tf(fmaxf(fmaf(dy * rstd, gg.y, bb.y), 0.f));
        o4.z = f2tf(fmaxf(fmaf(dz * rstd, gg.z, bb.z), 0.f));
        o4.w = f2tf(fmaxf(fmaf(dw * rstd, gg.w, bb.w), 0.f));
        *(float4*)(As + r * AP + lane * 4) = o4;
    }

    // warp tile: warp_m 0..3 (m32 each), warp_n 0..3 (n32 each)
    int warp_m = w & 3;
    int warp_n = w >> 2;
    int m0 = warp_m * 32;
    int nb = warp_n * 32;

    float4 c[2][4];
    #pragma unroll
    for (int mt = 0; mt < 2; mt++)
        #pragma unroll
        for (int nt = 0; nt < 4; nt++) c[mt][nt] = make_float4(0.f, 0.f, 0.f, 0.f);

    for (int k0 = 0; k0 < DD; k0 += KT) {
        __syncthreads();
        // stage W[k0:k0+KT, :] into Ws with tf32 rounding (512 thr)
        for (int idx = tid; idx < KT * DD / 4; idx += 512) {
            int kk = idx >> 5;          // DD/4 = 32
            int c4 = idx & 31;
            float4 wv = *(const float4*)(W + (size_t)(k0 + kk) * DD + c4 * 4);
            wv.x = f2tf(wv.x); wv.y = f2tf(wv.y); wv.z = f2tf(wv.z); wv.w = f2tf(wv.w);
            *(float4*)(Ws + kk * WP + c4 * 4) = wv;
        }
        __syncthreads();

        #pragma unroll
        for (int ks = 0; ks < KT / 8; ks++) {
            int kb = ks * 8;
            int ka = k0 + kb;          // global k offset into As
            uint32_t a[2][4];
            #pragma unroll
            for (int mt = 0; mt < 2; mt++) {
                int ra = m0 + mt * 16 + qid;
                a[mt][0] = __float_as_uint(As[ra * AP + ka + tq]);
                a[mt][1] = __float_as_uint(As[(ra + 8) * AP + ka + tq]);
                a[mt][2] = __float_as_uint(As[ra * AP + ka + tq + 4]);
                a[mt][3] = __float_as_uint(As[(ra + 8) * AP + ka + tq + 4]);
            }
            #pragma unroll
            for (int nt = 0; nt < 4; nt++) {
                int col = nb + nt * 8 + qid;
                uint32_t b0 = __float_as_uint(Ws[(kb + tq) * WP + col]);
                uint32_t b1 = __float_as_uint(Ws[(kb + tq + 4) * WP + col]);
                mma_tf32(c[0][nt], a[0][0], a[0][1], a[0][2], a[0][3], b0, b1);
                mma_tf32(c[1][nt], a[1][0], a[1][1], a[1][2], a[1][3], b0, b1);
            }
        }
    }

    // epilogue: scale by dinv[row], write float2 pairs
    #pragma unroll
    for (int mt = 0; mt < 2; mt++) {
        int ra = row0 + m0 + mt * 16 + qid;
        int rb = ra + 8;
        float dva = (ra < NN) ? g_dinv[ra] : 0.f;
        float dvb = (rb < NN) ? g_dinv[rb] : 0.f;
        #pragma unroll
        for (int nt = 0; nt < 4; nt++) {
            int col = nb + nt * 8 + 2 * tq;
            if (ra < NN) {
                float2 o = make_float2(c[mt][nt].x * dva, c[mt][nt].y * dva);
                *(float2*)(tout + (size_t)ra * DD + col) = o;
            }
            if (rb < NN) {
                float2 o = make_float2(c[mt][nt].z * dvb, c[mt][nt].w * dvb);
                *(float2*)(tout + (size_t)rb * DD + col) = o;
            }
        }
    }
}

// ---------------- per-node gather accumulate ----------------------------------
// out[i] = b + dinv[i]*(tin[i] + sum_{e in CSR[i]} tin[src_e]) (+ res[i])
__global__ void __launch_bounds__(256) k_accum(const float* __restrict__ tin,
                        float* __restrict__ out,
                        const float* __restrict__ b,
                        const float* __restrict__ res) {
    int node = (blockIdx.x * blockDim.x + threadIdx.x) >> 5;
    int lane = threadIdx.x & 31;
    if (node >= NN) return;

    const float4* T = (const float4*)tin;
    int s0 = g_start[node];
    int cnt = g_cnt[node];

    float4 a[8];
    a[0] = T[(size_t)node * 32 + lane];
    #pragma unroll
    for (int j = 1; j < 8; j++) a[j] = make_float4(0.f, 0.f, 0.f, 0.f);

    int e = 0;
    for (; e + 8 <= cnt; e += 8) {
        int idx[8];
        #pragma unroll
        for (int j = 0; j < 8; j++) idx[j] = g_esrc[s0 + e + j];
        #pragma unroll
        for (int j = 0; j < 8; j++) {
            float4 v = T[(size_t)idx[j] * 32 + lane];
            a[j].x += v.x; a[j].y += v.y; a[j].z += v.z; a[j].w += v.w;
        }
    }
    for (; e < cnt; e++) {
        int i0 = g_esrc[s0 + e];
        float4 v = T[(size_t)i0 * 32 + lane];
        a[0].x += v.x; a[0].y += v.y; a[0].z += v.z; a[0].w += v.w;
    }
    #pragma unroll
    for (int j = 1; j < 8; j++) {
        a[0].x += a[j].x; a[0].y += a[j].y; a[0].z += a[j].z; a[0].w += a[j].w;
    }

    float dv = g_dinv[node];
    float4 bb = ((const float4*)b)[lane];
    float4 o;
    o.x = fmaf(dv, a[0].x, bb.x);
    o.y = fmaf(dv, a[0].y, bb.y);
    o.z = fmaf(dv, a[0].z, bb.z);
    o.w = fmaf(dv, a[0].w, bb.w);
    if (res) {
        float4 r = ((const float4*)(res))[(size_t)node * 32 + lane];
        o.x += r.x; o.y += r.y; o.z += r.z; o.w += r.w;
    }
    ((float4*)out)[(size_t)node * 32 + lane] = o;
}

// ---------------- launch ------------------------------------------------------
extern "C" void kernel_launch(void* const* d_in, const int* in_sizes, int n_in,
                              void* d_out, int out_size) {
    const float* x   = (const float*)d_in[0];
    const int*   ei  = (const int*)d_in[1];
    const int*   src = ei;
    const int*   dst = ei + EE;
    const float* lng0 = (const float*)d_in[2];
    const float* lnb0 = (const float*)d_in[3];
    const float* W0   = (const float*)d_in[4];
    const float* b0   = (const float*)d_in[5];
    const float* lng1 = (const float*)d_in[6];
    const float* lnb1 = (const float*)d_in[7];
    const float* W1   = (const float*)d_in[8];
    const float* b1   = (const float*)d_in[9];
    const float* lng2 = (const float*)d_in[10];
    const float* lnb2 = (const float*)d_in[11];
    const float* W2   = (const float*)d_in[12];
    const float* b2   = (const float*)d_in[13];
    float* out = (float*)d_out;

    float* d_tA;  cudaGetSymbolAddress((void**)&d_tA, g_tmpA);
    float* d_tB;  cudaGetSymbolAddress((void**)&d_tB, g_tmpB);
    float* d_x1;  cudaGetSymbolAddress((void**)&d_x1, g_x1);

    cudaFuncSetAttribute(k_ln_gemm, cudaFuncAttributeMaxDynamicSharedMemorySize, SMEM_BYTES);

    const int gemm_blocks = (NN + BM - 1) / BM;   // 391
    const int acc_blocks = (NN * 32 + 255) / 256;

    // prep part 1 (dinv needed by gemm0)
    k_zero<<<(NN + 255) / 256, 256>>>();
    k_hist<<<(EE + 255) / 256, 256>>>(dst);
    k_dinv<<<(NN + 255) / 256, 256>>>();

    // layer 0 GEMM (launch #4 -> ncu profile slot): x -> tA
    k_ln_gemm<<<gemm_blocks, 512, SMEM_BYTES>>>(x, lng0, lnb0, W0, d_tA);

    // prep part 2 (CSR for accum)
    k_scan_a<<<SNB, SCH>>>();
    k_scan_c<<<SNB, SCH>>>();
    k_bucket<<<(EE + 255) / 256, 256>>>(src, dst);

    // layer 0 accum: tA (+x) -> x1
    k_accum<<<acc_blocks, 256>>>(d_tA, d_x1, b0, x);

    // layer 1: x1 -> tB ; accum -> tA (h2)
    k_ln_gemm<<<gemm_blocks, 512, SMEM_BYTES>>>(d_x1, lng1, lnb1, W1, d_tB);
    k_accum<<<acc_blocks, 256>>>(d_tB, d_tA, b1, nullptr);

    // layer 2: tA -> tB ; accum (+x1) -> out
    k_ln_gemm<<<gemm_blocks, 512, SMEM_BYTES>>>(d_tA, lng2, lnb2, W2, d_tB);
    k_accum<<<acc_blocks, 256>>>(d_tB, out, b2, d_x1);
}

// round 11
// speedup vs baseline: 1.4263x; 1.1325x over previous
#include <cuda_runtime.h>
#include <cuda_fp16.h>
#include <cstdint>

#define NN 50000
#define DD 128
#define EE 800000
#define EPSL 1e-5f

#define SCH 512
#define SNB ((NN + SCH - 1) / SCH)   // 98

// GEMM tiling (fp16 MMA)
#define BM 128
#define KT 64
#define APH 136                       // As row stride in halves (272B rows)
#define WPH 136                       // Ws row stride in halves
#define SMEM_BYTES ((BM * APH + KT * WPH) * 2)   // 52224 B

// ---------------- scratch (device globals; no allocation allowed) -------------
__device__ float  g_dinv[NN];
__device__ __half g_tmpA[NN * DD];    // fp16 messages: dinv[i]*(ReLU(LN(h))@W)
__device__ __half g_tmpB[NN * DD];
__device__ float  g_x1[NN * DD];      // x after layer0 + residual
__device__ float  g_h2[NN * DD];      // layer1 output
__device__ int    g_cnt[NN];
__device__ int    g_start[NN];
__device__ int    g_cursor[NN];
__device__ int    g_esrc[EE];
__device__ int    g_csum[SNB];

// ---------------- CSR build ----------------------------------------------------
__global__ void k_zero() {
    int i = blockIdx.x * blockDim.x + threadIdx.x;
    if (i < NN) g_cnt[i] = 0;
}

__global__ void k_hist(const int* __restrict__ dst) {
    int e = blockIdx.x * blockDim.x + threadIdx.x;
    if (e < EE) atomicAdd(&g_cnt[dst[e]], 1);
}

__global__ void k_dinv() {
    int i = blockIdx.x * blockDim.x + threadIdx.x;
    if (i < NN) g_dinv[i] = rsqrtf(1.0f + (float)g_cnt[i]);
}

__global__ void __launch_bounds__(SCH) k_scan_a() {
    __shared__ int sm[SCH];
    int t = threadIdx.x;
    int i = blockIdx.x * SCH + t;
    sm[t] = (i < NN) ? g_cnt[i] : 0;
    __syncthreads();
    for (int off = SCH / 2; off > 0; off >>= 1) {
        if (t < off) sm[t] += sm[t + off];
        __syncthreads();
    }
    if (t == 0) g_csum[blockIdx.x] = sm[0];
}

__global__ void __launch_bounds__(SCH) k_scan_c() {
    __shared__ int sm[SCH];
    __shared__ int base;
    int t = threadIdx.x;
    int i = blockIdx.x * SCH + t;
    int v = (i < NN) ? g_cnt[i] : 0;
    sm[t] = v;
    if (t == 0) {
        int run = 0;
        for (int j = 0; j < blockIdx.x; j++) run += g_csum[j];
        base = run;
    }
    __syncthreads();
    for (int off = 1; off < SCH; off <<= 1) {
        int x = (t >= off) ? sm[t - off] : 0;
        __syncthreads();
        sm[t] += x;
        __syncthreads();
    }
    if (i < NN) {
        int excl = sm[t] - v + base;
        g_start[i] = excl;
        g_cursor[i] = excl;
    }
}

__global__ void k_bucket(const int* __restrict__ src, const int* __restrict__ dst) {
    int e = blockIdx.x * blockDim.x + threadIdx.x;
    if (e < EE) {
        int pos = atomicAdd(&g_cursor[dst[e]], 1);
        g_esrc[pos] = src[e];
    }
}

// ---------------- MMA helpers ---------------------------------------------------
__device__ __forceinline__ uint32_t smem_u32(const void* p) {
    return (uint32_t)__cvta_generic_to_shared(p);
}

__device__ __forceinline__ void ldmatrix_x4(uint32_t& r0, uint32_t& r1,
                                            uint32_t& r2, uint32_t& r3, uint32_t addr) {
    asm volatile("ldmatrix.sync.aligned.m8n8.x4.shared.b16 {%0,%1,%2,%3}, [%4];"
                 : "=r"(r0), "=r"(r1), "=r"(r2), "=r"(r3) : "r"(addr));
}

__device__ __forceinline__ void ldmatrix_x2_trans(uint32_t& r0, uint32_t& r1, uint32_t addr) {
    asm volatile("ldmatrix.sync.aligned.m8n8.x2.trans.shared.b16 {%0,%1}, [%2];"
                 : "=r"(r0), "=r"(r1) : "r"(addr));
}

__device__ __forceinline__ void mma_f16(float4& c, uint32_t a0, uint32_t a1,
                                        uint32_t a2, uint32_t a3,
                                        uint32_t b0, uint32_t b1) {
    asm volatile("mma.sync.aligned.m16n8k16.row.col.f32.f16.f16.f32 "
                 "{%0,%1,%2,%3}, {%4,%5,%6,%7}, {%8,%9}, {%0,%1,%2,%3};"
                 : "+f"(c.x), "+f"(c.y), "+f"(c.z), "+f"(c.w)
                 : "r"(a0), "r"(a1), "r"(a2), "r"(a3), "r"(b0), "r"(b1));
}

// ---------------- fused LN + ReLU + fp16 GEMM + dinv prescale ------------------
// tout[i] = half( dinv[i] * ( ReLU( LN(h_i)*g + bt ) @ W ) )
// Block 512 thr (16 warps); tile M=128 x N=128; warp tile m32 x n32.
__global__ void __launch_bounds__(512) k_ln_gemm(const float* __restrict__ h,
                          const float* __restrict__ g,
                          const float* __restrict__ bt,
                          const float* __restrict__ W,
                          __half* __restrict__ tout) {
    extern __shared__ __half smh[];
    __half* As = smh;                 // [BM][APH] halves
    __half* Ws = smh + BM * APH;      // [KT][WPH] halves

    int tid = threadIdx.x;
    int lane = tid & 31;
    int w = tid >> 5;           // 0..15
    int qid = lane >> 2;        // 0..7
    int tq = lane & 3;          // 0..3
    int row0 = blockIdx.x * BM;

    // --- LN + ReLU phase -> fp16 As; warp w handles rows w, w+16, ..., w+112 ---
    for (int r = w; r < BM; r += 16) {
        int row = row0 + r;
        float4 v = make_float4(0.f, 0.f, 0.f, 0.f);
        if (row < NN) v = ((const float4*)(h + (size_t)row * DD))[lane];
        float s = v.x + v.y + v.z + v.w;
        #pragma unroll
        for (int o = 16; o; o >>= 1) s += __shfl_xor_sync(0xffffffffu, s, o);
        float mu = s * (1.0f / DD);
        float dx = v.x - mu, dy = v.y - mu, dz = v.z - mu, dw = v.w - mu;
        float q = dx * dx + dy * dy + dz * dz + dw * dw;
        #pragma unroll
        for (int o = 16; o; o >>= 1) q += __shfl_xor_sync(0xffffffffu, q, o);
        float rstd = rsqrtf(q * (1.0f / DD) + EPSL);
        float4 gg = ((const float4*)g)[lane];
        float4 bb = ((const float4*)bt)[lane];
        __half2 h2a = __floats2half2_rn(fmaxf(fmaf(dx * rstd, gg.x, bb.x), 0.f),
                                        fmaxf(fmaf(dy * rstd, gg.y, bb.y), 0.f));
        __half2 h2b = __floats2half2_rn(fmaxf(fmaf(dz * rstd, gg.z, bb.z), 0.f),
                                        fmaxf(fmaf(dw * rstd, gg.w, bb.w), 0.f));
        uint2 u;
        u.x = *(uint32_t*)&h2a;
        u.y = *(uint32_t*)&h2b;
        *(uint2*)(As + r * APH + lane * 4) = u;
    }

    // warp tile: warp_m 0..3 (m32), warp_n 0..3 (n32)
    int warp_m = w & 3;
    int warp_n = w >> 2;
    int m0 = warp_m * 32;
    int nb = warp_n * 32;

    float4 c[2][4];
    #pragma unroll
    for (int mt = 0; mt < 2; mt++)
        #pragma unroll
        for (int nt = 0; nt < 4; nt++) c[mt][nt] = make_float4(0.f, 0.f, 0.f, 0.f);

    // ldmatrix lane addressing
    // A (x4): lanes 0-7 rows 0-7 col+0; 8-15 rows 8-15 col+0; 16-23 rows 0-7 col+8; 24-31 rows 8-15 col+8
    int a_row = (lane & 7) + 8 * ((lane >> 3) & 1);
    int a_col8 = 8 * (lane >> 4);
    // B (x2 trans): lanes 0-15 rows k 0-15 at col nbf
    int b_row = lane & 15;

    for (int k0 = 0; k0 < DD; k0 += KT) {
        __syncthreads();
        // stage W[k0:k0+KT, :] -> Ws as fp16
        for (int idx = tid; idx < KT * DD / 4; idx += 512) {
            int kk = idx >> 5;          // DD/4 = 32
            int c4 = idx & 31;
            float4 wv = *(const float4*)(W + (size_t)(k0 + kk) * DD + c4 * 4);
            __half2 p0 = __floats2half2_rn(wv.x, wv.y);
            __half2 p1 = __floats2half2_rn(wv.z, wv.w);
            uint2 u;
            u.x = *(uint32_t*)&p0;
            u.y = *(uint32_t*)&p1;
            *(uint2*)(Ws + kk * WPH + c4 * 4) = u;
        }
        __syncthreads();

        #pragma unroll
        for (int ks = 0; ks < KT / 16; ks++) {
            int kb = ks * 16;           // local k in Ws
            int ka = k0 + kb;           // global k in As
            uint32_t a[2][4];
            #pragma unroll
            for (int mt = 0; mt < 2; mt++) {
                uint32_t addr = smem_u32(As + (m0 + mt * 16 + a_row) * APH + ka + a_col8);
                ldmatrix_x4(a[mt][0], a[mt][1], a[mt][2], a[mt][3], addr);
            }
            uint32_t b[4][2];
            #pragma unroll
            for (int nt = 0; nt < 4; nt++) {
                int nbf = nb + nt * 8;
                uint32_t addr = smem_u32(Ws + (kb + b_row) * WPH + nbf);
                ldmatrix_x2_trans(b[nt][0], b[nt][1], addr);
            }
            #pragma unroll
            for (int mt = 0; mt < 2; mt++)
                #pragma unroll
                for (int nt = 0; nt < 4; nt++)
                    mma_f16(c[mt][nt], a[mt][0], a[mt][1], a[mt][2], a[mt][3],
                            b[nt][0], b[nt][1]);
        }
    }

    // epilogue: scale by dinv[row], write half2 pairs
    #pragma unroll
    for (int mt = 0; mt < 2; mt++) {
        int ra = row0 + m0 + mt * 16 + qid;
        int rb = ra + 8;
        float dva = (ra < NN) ? g_dinv[ra] : 0.f;
        float dvb = (rb < NN) ? g_dinv[rb] : 0.f;
        #pragma unroll
        for (int nt = 0; nt < 4; nt++) {
            int col = nb + nt * 8 + 2 * tq;
            if (ra < NN) {
                __half2 o = __floats2half2_rn(c[mt][nt].x * dva, c[mt][nt].y * dva);
                *(uint32_t*)(tout + (size_t)ra * DD + col) = *(uint32_t*)&o;
            }
            if (rb < NN) {
                __half2 o = __floats2half2_rn(c[mt][nt].z * dvb, c[mt][nt].w * dvb);
                *(uint32_t*)(tout + (size_t)rb * DD + col) = *(uint32_t*)&o;
            }
        }
    }
}

// ---------------- per-node gather accumulate (fp16 messages -> fp32 out) -------
// out[i] = b + dinv[i]*(tin[i] + sum_{e in CSR[i]} tin[src_e]) (+ res[i])
__global__ void __launch_bounds__(256) k_accum(const __half* __restrict__ tin,
                        float* __restrict__ out,
                        const float* __restrict__ b,
                        const float* __restrict__ res) {
    int node = (blockIdx.x * blockDim.x + threadIdx.x) >> 5;
    int lane = threadIdx.x & 31;
    if (node >= NN) return;

    const uint2* T = (const uint2*)tin;   // 4 halves per lane
    int s0 = g_start[node];
    int cnt = g_cnt[node];

    float4 a[8];
    {
        uint2 u = T[(size_t)node * 32 + lane];
        float2 f0 = __half22float2(*(__half2*)&u.x);
        float2 f1 = __half22float2(*(__half2*)&u.y);
        a[0] = make_float4(f0.x, f0.y, f1.x, f1.y);
    }
    #pragma unroll
    for (int j = 1; j < 8; j++) a[j] = make_float4(0.f, 0.f, 0.f, 0.f);

    int e = 0;
    for (; e + 8 <= cnt; e += 8) {
        int idx[8];
        #pragma unroll
        for (int j = 0; j < 8; j++) idx[j] = g_esrc[s0 + e + j];
        #pragma unroll
        for (int j = 0; j < 8; j++) {
            uint2 u = T[(size_t)idx[j] * 32 + lane];
            float2 f0 = __half22float2(*(__half2*)&u.x);
            float2 f1 = __half22float2(*(__half2*)&u.y);
            a[j].x += f0.x; a[j].y += f0.y; a[j].z += f1.x; a[j].w += f1.y;
        }
    }
    for (; e < cnt; e++) {
        int i0 = g_esrc[s0 + e];
        uint2 u = T[(size_t)i0 * 32 + lane];
        float2 f0 = __half22float2(*(__half2*)&u.x);
        float2 f1 = __half22float2(*(__half2*)&u.y);
        a[0].x += f0.x; a[0].y += f0.y; a[0].z += f1.x; a[0].w += f1.y;
    }
    #pragma unroll
    for (int j = 1; j < 8; j++) {
        a[0].x += a[j].x; a[0].y += a[j].y; a[0].z += a[j].z; a[0].w += a[j].w;
    }

    float dv = g_dinv[node];
    float4 bb = ((const float4*)b)[lane];
    float4 o;
    o.x = fmaf(dv, a[0].x, bb.x);
    o.y = fmaf(dv, a[0].y, bb.y);
    o.z = fmaf(dv, a[0].z, bb.z);
    o.w = fmaf(dv, a[0].w, bb.w);
    if (res) {
        float4 r = ((const float4*)(res))[(size_t)node * 32 + lane];
        o.x += r.x; o.y += r.y; o.z += r.z; o.w += r.w;
    }
    ((float4*)out)[(size_t)node * 32 + lane] = o;
}

// ---------------- launch ------------------------------------------------------
extern "C" void kernel_launch(void* const* d_in, const int* in_sizes, int n_in,
                              void* d_out, int out_size) {
    const float* x   = (const float*)d_in[0];
    const int*   ei  = (const int*)d_in[1];
    const int*   src = ei;
    const int*   dst = ei + EE;
    const float* lng0 = (const float*)d_in[2];
    const float* lnb0 = (const float*)d_in[3];
    const float* W0   = (const float*)d_in[4];
    const float* b0   = (const float*)d_in[5];
    const float* lng1 = (const float*)d_in[6];
    const float* lnb1 = (const float*)d_in[7];
    const float* W1   = (const float*)d_in[8];
    const float* b1   = (const float*)d_in[9];
    const float* lng2 = (const float*)d_in[10];
    const float* lnb2 = (const float*)d_in[11];
    const float* W2   = (const float*)d_in[12];
    const float* b2   = (const float*)d_in[13];
    float* out = (float*)d_out;

    __half* d_tA; cudaGetSymbolAddress((void**)&d_tA, g_tmpA);
    __half* d_tB; cudaGetSymbolAddress((void**)&d_tB, g_tmpB);
    float*  d_x1; cudaGetSymbolAddress((void**)&d_x1, g_x1);
    float*  d_h2; cudaGetSymbolAddress((void**)&d_h2, g_h2);

    cudaFuncSetAttribute(k_ln_gemm, cudaFuncAttributeMaxDynamicSharedMemorySize, SMEM_BYTES);

    const int gemm_blocks = (NN + BM - 1) / BM;   // 391
    const int acc_blocks = (NN * 32 + 255) / 256;

    // prep part 1 (dinv needed by gemm0)
    k_zero<<<(NN + 255) / 256, 256>>>();
    k_hist<<<(EE + 255) / 256, 256>>>(dst);
    k_dinv<<<(NN + 255) / 256, 256>>>();

    // layer 0 GEMM (launch #4 -> ncu profile slot): x -> tA
    k_ln_gemm<<<gemm_blocks, 512, SMEM_BYTES>>>(x, lng0, lnb0, W0, d_tA);

    // prep part 2 (CSR for accum)
    k_scan_a<<<SNB, SCH>>>();
    k_scan_c<<<SNB, SCH>>>();
    k_bucket<<<(EE + 255) / 256, 256>>>(src, dst);

    // layer 0 accum: tA (+x) -> x1
    k_accum<<<acc_blocks, 256>>>(d_tA, d_x1, b0, x);

    // layer 1: x1 -> tB ; accum -> h2
    k_ln_gemm<<<gemm_blocks, 512, SMEM_BYTES>>>(d_x1, lng1, lnb1, W1, d_tB);
    k_accum<<<acc_blocks, 256>>>(d_tB, d_h2, b1, nullptr);

    // layer 2: h2 -> tA ; accum (+x1) -> out
    k_ln_gemm<<<gemm_blocks, 512, SMEM_BYTES>>>(d_h2, lng2, lnb2, W2, d_tA);
    k_accum<<<acc_blocks, 256>>>(d_tA, out, b2, d_x1);
}

// round 12
// speedup vs baseline: 1.4557x; 1.0206x over previous
#include <cuda_runtime.h>
#include <cuda_fp16.h>
#include <cstdint>

#define NN 50000
#define DD 128
#define EE 800000
#define EPSL 1e-5f

#define SCH 512
#define SNB ((NN + SCH - 1) / SCH)   // 98

// GEMM tiling (fp16 MMA, full-K resident)
#define BM 128
#define APH 136                       // As row stride in halves (272B rows)
#define WPH 136                       // Ws row stride in halves
#define SMEM_BYTES ((BM * APH + DD * WPH) * 2)   // 69632 B

// ---------------- scratch (device globals; no allocation allowed) -------------
__device__ float  g_dinv[NN];
__device__ __half g_tmpA[NN * DD];    // fp16 messages: dinv[i]*(ReLU(LN(h))@W)
__device__ __half g_tmpB[NN * DD];
__device__ float  g_x1[NN * DD];      // x after layer0 + residual
__device__ float  g_h2[NN * DD];      // layer1 output
__device__ int    g_cnt[NN];
__device__ int    g_start[NN];
__device__ int    g_cursor[NN];
__device__ int    g_esrc[EE];
__device__ int    g_csum[SNB];

// ---------------- CSR build ----------------------------------------------------
__global__ void k_zero() {
    int i = blockIdx.x * blockDim.x + threadIdx.x;
    if (i < NN) g_cnt[i] = 0;
}

__global__ void k_hist(const int* __restrict__ dst) {
    int e = blockIdx.x * blockDim.x + threadIdx.x;
    if (e < EE) atomicAdd(&g_cnt[dst[e]], 1);
}

__global__ void k_dinv() {
    int i = blockIdx.x * blockDim.x + threadIdx.x;
    if (i < NN) g_dinv[i] = rsqrtf(1.0f + (float)g_cnt[i]);
}

__global__ void __launch_bounds__(SCH) k_scan_a() {
    __shared__ int sm[SCH];
    int t = threadIdx.x;
    int i = blockIdx.x * SCH + t;
    sm[t] = (i < NN) ? g_cnt[i] : 0;
    __syncthreads();
    for (int off = SCH / 2; off > 0; off >>= 1) {
        if (t < off) sm[t] += sm[t + off];
        __syncthreads();
    }
    if (t == 0) g_csum[blockIdx.x] = sm[0];
}

__global__ void __launch_bounds__(SCH) k_scan_c() {
    __shared__ int sm[SCH];
    __shared__ int base;
    int t = threadIdx.x;
    int i = blockIdx.x * SCH + t;
    int v = (i < NN) ? g_cnt[i] : 0;
    sm[t] = v;
    if (t == 0) {
        int run = 0;
        for (int j = 0; j < blockIdx.x; j++) run += g_csum[j];
        base = run;
    }
    __syncthreads();
    for (int off = 1; off < SCH; off <<= 1) {
        int x = (t >= off) ? sm[t - off] : 0;
        __syncthreads();
        sm[t] += x;
        __syncthreads();
    }
    if (i < NN) {
        int excl = sm[t] - v + base;
        g_start[i] = excl;
        g_cursor[i] = excl;
    }
}

__global__ void k_bucket(const int* __restrict__ src, const int* __restrict__ dst) {
    int e = blockIdx.x * blockDim.x + threadIdx.x;
    if (e < EE) {
        int pos = atomicAdd(&g_cursor[dst[e]], 1);
        g_esrc[pos] = src[e];
    }
}

// ---------------- MMA helpers ---------------------------------------------------
__device__ __forceinline__ uint32_t smem_u32(const void* p) {
    return (uint32_t)__cvta_generic_to_shared(p);
}

__device__ __forceinline__ void ldmatrix_x4(uint32_t& r0, uint32_t& r1,
                                            uint32_t& r2, uint32_t& r3, uint32_t addr) {
    asm volatile("ldmatrix.sync.aligned.m8n8.x4.shared.b16 {%0,%1,%2,%3}, [%4];"
                 : "=r"(r0), "=r"(r1), "=r"(r2), "=r"(r3) : "r"(addr));
}

__device__ __forceinline__ void ldmatrix_x2_trans(uint32_t& r0, uint32_t& r1, uint32_t addr) {
    asm volatile("ldmatrix.sync.aligned.m8n8.x2.trans.shared.b16 {%0,%1}, [%2];"
                 : "=r"(r0), "=r"(r1) : "r"(addr));
}

__device__ __forceinline__ void mma_f16(float4& c, uint32_t a0, uint32_t a1,
                                        uint32_t a2, uint32_t a3,
                                        uint32_t b0, uint32_t b1) {
    asm volatile("mma.sync.aligned.m16n8k16.row.col.f32.f16.f16.f32 "
                 "{%0,%1,%2,%3}, {%4,%5,%6,%7}, {%8,%9}, {%0,%1,%2,%3};"
                 : "+f"(c.x), "+f"(c.y), "+f"(c.z), "+f"(c.w)
                 : "r"(a0), "r"(a1), "r"(a2), "r"(a3), "r"(b0), "r"(b1));
}

// ---------------- fused LN + ReLU + fp16 GEMM + dinv prescale ------------------
// tout[i] = half( dinv[i] * ( ReLU( LN(h_i)*g + bt ) @ W ) )
// Block 512 thr (16 warps); tile M=128 x N=128; warp tile m32 x n32.
// Full K resident in smem: ONE barrier, then 8 unbroken MMA k-steps.
__global__ void __launch_bounds__(512) k_ln_gemm(const float* __restrict__ h,
                          const float* __restrict__ g,
                          const float* __restrict__ bt,
                          const float* __restrict__ W,
                          __half* __restrict__ tout) {
    extern __shared__ __half smh[];
    __half* As = smh;                 // [BM][APH] halves
    __half* Ws = smh + BM * APH;      // [DD][WPH] halves

    int tid = threadIdx.x;
    int lane = tid & 31;
    int w = tid >> 5;           // 0..15
    int qid = lane >> 2;        // 0..7
    int tq = lane & 3;          // 0..3
    int row0 = blockIdx.x * BM;

    // --- LN + ReLU -> fp16 As; warp w handles rows w, w+16, ..., w+112 ---
    for (int r = w; r < BM; r += 16) {
        int row = row0 + r;
        float4 v = make_float4(0.f, 0.f, 0.f, 0.f);
        if (row < NN) v = ((const float4*)(h + (size_t)row * DD))[lane];
        float s = v.x + v.y + v.z + v.w;
        #pragma unroll
        for (int o = 16; o; o >>= 1) s += __shfl_xor_sync(0xffffffffu, s, o);
        float mu = s * (1.0f / DD);
        float dx = v.x - mu, dy = v.y - mu, dz = v.z - mu, dw = v.w - mu;
        float q = dx * dx + dy * dy + dz * dz + dw * dw;
        #pragma unroll
        for (int o = 16; o; o >>= 1) q += __shfl_xor_sync(0xffffffffu, q, o);
        float rstd = rsqrtf(q * (1.0f / DD) + EPSL);
        float4 gg = ((const float4*)g)[lane];
        float4 bb = ((const float4*)bt)[lane];
        __half2 h2a = __floats2half2_rn(fmaxf(fmaf(dx * rstd, gg.x, bb.x), 0.f),
                                        fmaxf(fmaf(dy * rstd, gg.y, bb.y), 0.f));
        __half2 h2b = __floats2half2_rn(fmaxf(fmaf(dz * rstd, gg.z, bb.z), 0.f),
                                        fmaxf(fmaf(dw * rstd, gg.w, bb.w), 0.f));
        uint2 u;
        u.x = *(uint32_t*)&h2a;
        u.y = *(uint32_t*)&h2b;
        *(uint2*)(As + r * APH + lane * 4) = u;
    }

    // --- stage full W (128x128) -> Ws as fp16 ---
    for (int idx = tid; idx < DD * DD / 4; idx += 512) {
        int kk = idx >> 5;          // DD/4 = 32
        int c4 = idx & 31;
        float4 wv = *(const float4*)(W + (size_t)kk * DD + c4 * 4);
        __half2 p0 = __floats2half2_rn(wv.x, wv.y);
        __half2 p1 = __floats2half2_rn(wv.z, wv.w);
        uint2 u;
        u.x = *(uint32_t*)&p0;
        u.y = *(uint32_t*)&p1;
        *(uint2*)(Ws + kk * WPH + c4 * 4) = u;
    }

    __syncthreads();   // the only barrier

    // warp tile: warp_m 0..3 (m32), warp_n 0..3 (n32)
    int warp_m = w & 3;
    int warp_n = w >> 2;
    int m0 = warp_m * 32;
    int nb = warp_n * 32;

    float4 c[2][4];
    #pragma unroll
    for (int mt = 0; mt < 2; mt++)
        #pragma unroll
        for (int nt = 0; nt < 4; nt++) c[mt][nt] = make_float4(0.f, 0.f, 0.f, 0.f);

    // ldmatrix lane addressing
    int a_row = (lane & 7) + 8 * ((lane >> 3) & 1);
    int a_col8 = 8 * (lane >> 4);
    int b_row = lane & 15;

    #pragma unroll
    for (int ks = 0; ks < DD / 16; ks++) {
        int kb = ks * 16;
        uint32_t a[2][4];
        #pragma unroll
        for (int mt = 0; mt < 2; mt++) {
            uint32_t addr = smem_u32(As + (m0 + mt * 16 + a_row) * APH + kb + a_col8);
            ldmatrix_x4(a[mt][0], a[mt][1], a[mt][2], a[mt][3], addr);
        }
        uint32_t b[4][2];
        #pragma unroll
        for (int nt = 0; nt < 4; nt++) {
            int nbf = nb + nt * 8;
            uint32_t addr = smem_u32(Ws + (kb + b_row) * WPH + nbf);
            ldmatrix_x2_trans(b[nt][0], b[nt][1], addr);
        }
        #pragma unroll
        for (int mt = 0; mt < 2; mt++)
            #pragma unroll
            for (int nt = 0; nt < 4; nt++)
                mma_f16(c[mt][nt], a[mt][0], a[mt][1], a[mt][2], a[mt][3],
                        b[nt][0], b[nt][1]);
    }

    // epilogue: scale by dinv[row], write half2 pairs
    #pragma unroll
    for (int mt = 0; mt < 2; mt++) {
        int ra = row0 + m0 + mt * 16 + qid;
        int rb = ra + 8;
        float dva = (ra < NN) ? g_dinv[ra] : 0.f;
        float dvb = (rb < NN) ? g_dinv[rb] : 0.f;
        #pragma unroll
        for (int nt = 0; nt < 4; nt++) {
            int col = nb + nt * 8 + 2 * tq;
            if (ra < NN) {
                __half2 o = __floats2half2_rn(c[mt][nt].x * dva, c[mt][nt].y * dva);
                *(uint32_t*)(tout + (size_t)ra * DD + col) = *(uint32_t*)&o;
            }
            if (rb < NN) {
                __half2 o = __floats2half2_rn(c[mt][nt].z * dvb, c[mt][nt].w * dvb);
                *(uint32_t*)(tout + (size_t)rb * DD + col) = *(uint32_t*)&o;
            }
        }
    }
}

// ---------------- per-node gather accumulate (fp16 messages -> fp32 out) -------
// out[i] = b + dinv[i]*(tin[i] + sum_{e in CSR[i]} tin[src_e]) (+ res[i])
__global__ void __launch_bounds__(256) k_accum(const __half* __restrict__ tin,
                        float* __restrict__ out,
                        const float* __restrict__ b,
                        const float* __restrict__ res) {
    int node = (blockIdx.x * blockDim.x + threadIdx.x) >> 5;
    int lane = threadIdx.x & 31;
    if (node >= NN) return;

    const uint2* T = (const uint2*)tin;   // 4 halves per lane
    int s0 = g_start[node];
    int cnt = g_cnt[node];

    float4 a[8];
    {
        uint2 u = T[(size_t)node * 32 + lane];
        float2 f0 = __half22float2(*(__half2*)&u.x);
        float2 f1 = __half22float2(*(__half2*)&u.y);
        a[0] = make_float4(f0.x, f0.y, f1.x, f1.y);
    }
    #pragma unroll
    for (int j = 1; j < 8; j++) a[j] = make_float4(0.f, 0.f, 0.f, 0.f);

    int e = 0;
    for (; e + 8 <= cnt; e += 8) {
        int idx[8];
        #pragma unroll
        for (int j = 0; j < 8; j++) idx[j] = g_esrc[s0 + e + j];
        #pragma unroll
        for (int j = 0; j < 8; j++) {
            uint2 u = T[(size_t)idx[j] * 32 + lane];
            float2 f0 = __half22float2(*(__half2*)&u.x);
            float2 f1 = __half22float2(*(__half2*)&u.y);
            a[j].x += f0.x; a[j].y += f0.y; a[j].z += f1.x; a[j].w += f1.y;
        }
    }
    for (; e < cnt; e++) {
        int i0 = g_esrc[s0 + e];
        uint2 u = T[(size_t)i0 * 32 + lane];
        float2 f0 = __half22float2(*(__half2*)&u.x);
        float2 f1 = __half22float2(*(__half2*)&u.y);
        a[0].x += f0.x; a[0].y += f0.y; a[0].z += f1.x; a[0].w += f1.y;
    }
    #pragma unroll
    for (int j = 1; j < 8; j++) {
        a[0].x += a[j].x; a[0].y += a[j].y; a[0].z += a[j].z; a[0].w += a[j].w;
    }

    float dv = g_dinv[node];
    float4 bb = ((const float4*)b)[lane];
    float4 o;
    o.x = fmaf(dv, a[0].x, bb.x);
    o.y = fmaf(dv, a[0].y, bb.y);
    o.z = fmaf(dv, a[0].z, bb.z);
    o.w = fmaf(dv, a[0].w, bb.w);
    if (res) {
        float4 r = ((const float4*)(res))[(size_t)node * 32 + lane];
        o.x += r.x; o.y += r.y; o.z += r.z; o.w += r.w;
    }
    ((float4*)out)[(size_t)node * 32 + lane] = o;
}

// ---------------- launch ------------------------------------------------------
extern "C" void kernel_launch(void* const* d_in, const int* in_sizes, int n_in,
                              void* d_out, int out_size) {
    const float* x   = (const float*)d_in[0];
    const int*   ei  = (const int*)d_in[1];
    const int*   src = ei;
    const int*   dst = ei + EE;
    const float* lng0 = (const float*)d_in[2];
    const float* lnb0 = (const float*)d_in[3];
    const float* W0   = (const float*)d_in[4];
    const float* b0   = (const float*)d_in[5];
    const float* lng1 = (const float*)d_in[6];
    const float* lnb1 = (const float*)d_in[7];
    const float* W1   = (const float*)d_in[8];
    const float* b1   = (const float*)d_in[9];
    const float* lng2 = (const float*)d_in[10];
    const float* lnb2 = (const float*)d_in[11];
    const float* W2   = (const float*)d_in[12];
    const float* b2   = (const float*)d_in[13];
    float* out = (float*)d_out;

    __half* d_tA; cudaGetSymbolAddress((void**)&d_tA, g_tmpA);
    __half* d_tB; cudaGetSymbolAddress((void**)&d_tB, g_tmpB);
    float*  d_x1; cudaGetSymbolAddress((void**)&d_x1, g_x1);
    float*  d_h2; cudaGetSymbolAddress((void**)&d_h2, g_h2);

    cudaFuncSetAttribute(k_ln_gemm, cudaFuncAttributeMaxDynamicSharedMemorySize, SMEM_BYTES);

    const int gemm_blocks = (NN + BM - 1) / BM;   // 391
    const int acc_blocks = (NN * 32 + 255) / 256;

    // prep part 1 (dinv needed by gemm0)
    k_zero<<<(NN + 255) / 256, 256>>>();
    k_hist<<<(EE + 255) / 256, 256>>>(dst);
    k_dinv<<<(NN + 255) / 256, 256>>>();

    // layer 0 GEMM (launch #4 -> ncu profile slot): x -> tA
    k_ln_gemm<<<gemm_blocks, 512, SMEM_BYTES>>>(x, lng0, lnb0, W0, d_tA);

    // prep part 2 (CSR for accum)
    k_scan_a<<<SNB, SCH>>>();
    k_scan_c<<<SNB, SCH>>>();
    k_bucket<<<(EE + 255) / 256, 256>>>(src, dst);

    // layer 0 accum: tA (+x) -> x1
    k_accum<<<acc_blocks, 256>>>(d_tA, d_x1, b0, x);

    // layer 1: x1 -> tB ; accum -> h2
    k_ln_gemm<<<gemm_blocks, 512, SMEM_BYTES>>>(d_x1, lng1, lnb1, W1, d_tB);
    k_accum<<<acc_blocks, 256>>>(d_tB, d_h2, b1, nullptr);

    // layer 2: h2 -> tA ; accum (+x1) -> out
    k_ln_gemm<<<gemm_blocks, 512, SMEM_BYTES>>>(d_h2, lng2, lnb2, W2, d_tA);
    k_accum<<<acc_blocks, 256>>>(d_tA, out, b2, d_x1);
}